// round 6
// baseline (speedup 1.0000x reference)
#include <cuda_runtime.h>
#include <cuda_bf16.h>
#include <stdint.h>

#define N_NODES  100000
#define N_EDGES  1600000
#define IN_C     128
#define HID      128
#define LAT      64
#define N_LAYERS 3
#define N_GRAPHS 1000

#define SCAN_B   512
#define SCAN_NB  ((N_NODES + SCAN_B - 1) / SCAN_B)   // 196

// ---------------- scratch (device globals; no allocation allowed) ----------------
__device__ __align__(16) float g_bufA[N_NODES * HID];
__device__ __align__(16) float g_bufB[N_NODES * HID];
__device__ __align__(16) float g_pool[N_GRAPHS * HID];
__device__ int   g_deg[N_NODES];
__device__ int   g_rowptr[N_NODES + 1];
__device__ int   g_cursor[N_NODES];
__device__ int   g_col[N_EDGES];
__device__ int   g_bsums[SCAN_NB];
__device__ int   g_is64;   // 1 if indices are int64 on device, 0 if int32

// index loader that works for either int32 or int64 device layout
__device__ __forceinline__ int idx_at(const void* p, long long i, int is64) {
    if (is64) return (int)((const long long*)p)[i];
    return ((const int*)p)[i];
}

// ---------------- packed f32x2 helpers (Blackwell FFMA2 path) ----------------
__device__ __forceinline__ unsigned long long pack2(float x) {
    unsigned long long r;
    asm("mov.b64 %0, {%1, %1};" : "=l"(r) : "f"(x));
    return r;
}
__device__ __forceinline__ void ffma2(unsigned long long& d,
                                      unsigned long long a,
                                      unsigned long long b) {
    asm("fma.rn.f32x2 %0, %1, %2, %0;" : "+l"(d) : "l"(a), "l"(b));
}
__device__ __forceinline__ float2 unpack2(unsigned long long v) {
    float2 f;
    asm("mov.b64 {%0, %1}, %2;" : "=f"(f.x), "=f"(f.y) : "l"(v));
    return f;
}

// ---------------- dtype detection (runs in-graph, deterministic) ----------------
__global__ void k_detect(const void* ei) {
    if (threadIdx.x == 0 && blockIdx.x == 0) {
        const long long* e64 = (const long long*)ei;
        int ok = 1;
        for (int i = 0; i < 256; i++) {
            long long v = e64[i];
            if (v < 0 || v >= N_NODES) { ok = 0; break; }
        }
        g_is64 = ok;
    }
}

// ---------------- init / CSR build ----------------
__global__ void k_zero() {
    int i = blockIdx.x * blockDim.x + threadIdx.x;
    if (i < N_NODES) g_deg[i] = 0;
    if (i < N_GRAPHS * HID) g_pool[i] = 0.0f;
}

__global__ void k_hist(const void* __restrict__ ei) {
    int e = blockIdx.x * blockDim.x + threadIdx.x;
    int is64 = g_is64;
    if (e < N_EDGES) {
        int dst = idx_at(ei, (long long)N_EDGES + e, is64);
        atomicAdd(&g_deg[dst], 1);
    }
}

__global__ void k_scan_local() {
    __shared__ int s[SCAN_B];
    int i = blockIdx.x * SCAN_B + threadIdx.x;
    int v = (i < N_NODES) ? g_deg[i] : 0;
    s[threadIdx.x] = v;
    __syncthreads();
    #pragma unroll
    for (int off = 1; off < SCAN_B; off <<= 1) {
        int t = (threadIdx.x >= off) ? s[threadIdx.x - off] : 0;
        __syncthreads();
        s[threadIdx.x] += t;
        __syncthreads();
    }
    if (i < N_NODES) g_rowptr[i] = s[threadIdx.x] - v;   // exclusive prefix
    if (threadIdx.x == SCAN_B - 1) g_bsums[blockIdx.x] = s[threadIdx.x];
}

__global__ void k_scan_bsums() {
    if (threadIdx.x == 0 && blockIdx.x == 0) {
        int acc = 0;
        for (int b = 0; b < SCAN_NB; b++) { int t = g_bsums[b]; g_bsums[b] = acc; acc += t; }
    }
}

__global__ void k_scan_add() {
    int i = blockIdx.x * SCAN_B + threadIdx.x;
    if (i < N_NODES) {
        int v = g_rowptr[i] + g_bsums[blockIdx.x];
        g_rowptr[i] = v;
        g_cursor[i] = v;
    }
    if (i == 0) g_rowptr[N_NODES] = N_EDGES;
}

__global__ void k_scatter(const void* __restrict__ ei) {
    int e = blockIdx.x * blockDim.x + threadIdx.x;
    int is64 = g_is64;
    if (e < N_EDGES) {
        int src = idx_at(ei, e, is64);
        int dst = idx_at(ei, (long long)N_EDGES + e, is64);
        int pos = atomicAdd(&g_cursor[dst], 1);
        g_col[pos] = src;
    }
}

// ---------------- aggregation: agg[n] = h[n] + sum_{e in CSR(n)} h[col[e]] ----------------
// warp per node; lane owns one float4 (4 features); 4-way unrolled gather for MLP
__global__ __launch_bounds__(256) void k_agg(const float* __restrict__ h,
                                             float* __restrict__ out) {
    int warp = (blockIdx.x * blockDim.x + threadIdx.x) >> 5;
    int lane = threadIdx.x & 31;
    if (warp >= N_NODES) return;
    const float4* h4 = (const float4*)h;
    float4 acc = h4[(size_t)warp * 32 + lane];
    int s = g_rowptr[warp];
    int e = g_rowptr[warp + 1];
    int j = s;
    for (; j + 3 < e; j += 4) {
        int s0 = g_col[j];
        int s1 = g_col[j + 1];
        int s2 = g_col[j + 2];
        int s3 = g_col[j + 3];
        float4 v0 = h4[(size_t)s0 * 32 + lane];
        float4 v1 = h4[(size_t)s1 * 32 + lane];
        float4 v2 = h4[(size_t)s2 * 32 + lane];
        float4 v3 = h4[(size_t)s3 * 32 + lane];
        acc.x += (v0.x + v1.x) + (v2.x + v3.x);
        acc.y += (v0.y + v1.y) + (v2.y + v3.y);
        acc.z += (v0.z + v1.z) + (v2.z + v3.z);
        acc.w += (v0.w + v1.w) + (v2.w + v3.w);
    }
    for (; j < e; j++) {
        int s0 = g_col[j];
        float4 v0 = h4[(size_t)s0 * 32 + lane];
        acc.x += v0.x; acc.y += v0.y; acc.z += v0.z; acc.w += v0.w;
    }
    ((float4*)out)[(size_t)warp * 32 + lane] = acc;
}

// ---------------- GEMM + bias + ReLU (FFMA2):  C = relu(A @ W + b) ----------------
// block: 64 rows x 128 cols, 256 threads, thread tile 4 rows x 8 cols (4 col-pairs),
// K chunked by 32. Accumulators are packed f32x2 column pairs -> fma.rn.f32x2.
__global__ __launch_bounds__(256) void k_gemm_relu(const float* __restrict__ A,
                                                   const float* __restrict__ W,
                                                   const float* __restrict__ bias,
                                                   float* __restrict__ C) {
    __shared__ __align__(16) float As[64][33];
    __shared__ __align__(16) float Ws[32][128];
    int tid = threadIdx.x;
    int cg = tid & 15;    // col group: cols cg*8 .. cg*8+7
    int rg = tid >> 4;    // row group: rows rg*4 .. rg*4+3
    int rowBase = blockIdx.x * 64;

    unsigned long long acc[4][4];   // [row][col-pair], each = 2 packed fp32
    #pragma unroll
    for (int r = 0; r < 4; r++)
        #pragma unroll
        for (int c = 0; c < 4; c++) acc[r][c] = 0ULL;

    for (int kk = 0; kk < 128; kk += 32) {
        // load A tile: 64x32
        #pragma unroll
        for (int i = 0; i < 8; i++) {
            int idx = tid + i * 256;            // 0..2047
            int r = idx >> 5, k = idx & 31;
            int row = rowBase + r;
            As[r][k] = (row < N_NODES) ? A[(size_t)row * 128 + kk + k] : 0.0f;
        }
        // load W tile: 32x128 (float4)
        #pragma unroll
        for (int i = 0; i < 4; i++) {
            int idx = tid + i * 256;            // 0..1023 float4s
            int k = idx >> 5;
            int c4 = idx & 31;
            ((float4*)&Ws[k][0])[c4] = ((const float4*)W)[(size_t)(kk + k) * 32 + c4];
        }
        __syncthreads();
        #pragma unroll
        for (int k = 0; k < 32; k++) {
            unsigned long long p0 = pack2(As[rg * 4 + 0][k]);
            unsigned long long p1 = pack2(As[rg * 4 + 1][k]);
            unsigned long long p2 = pack2(As[rg * 4 + 2][k]);
            unsigned long long p3 = pack2(As[rg * 4 + 3][k]);
            ulonglong2 wA = *(const ulonglong2*)&Ws[k][cg * 8];      // col pairs 0,1
            ulonglong2 wB = *(const ulonglong2*)&Ws[k][cg * 8 + 4];  // col pairs 2,3
            ffma2(acc[0][0], p0, wA.x); ffma2(acc[0][1], p0, wA.y);
            ffma2(acc[0][2], p0, wB.x); ffma2(acc[0][3], p0, wB.y);
            ffma2(acc[1][0], p1, wA.x); ffma2(acc[1][1], p1, wA.y);
            ffma2(acc[1][2], p1, wB.x); ffma2(acc[1][3], p1, wB.y);
            ffma2(acc[2][0], p2, wA.x); ffma2(acc[2][1], p2, wA.y);
            ffma2(acc[2][2], p2, wB.x); ffma2(acc[2][3], p2, wB.y);
            ffma2(acc[3][0], p3, wA.x); ffma2(acc[3][1], p3, wA.y);
            ffma2(acc[3][2], p3, wB.x); ffma2(acc[3][3], p3, wB.y);
        }
        __syncthreads();
    }

    float b[8];
    #pragma unroll
    for (int c = 0; c < 8; c++) b[c] = bias[cg * 8 + c];

    #pragma unroll
    for (int r = 0; r < 4; r++) {
        int row = rowBase + rg * 4 + r;
        if (row < N_NODES) {
            float2 f0 = unpack2(acc[r][0]);
            float2 f1 = unpack2(acc[r][1]);
            float2 f2 = unpack2(acc[r][2]);
            float2 f3 = unpack2(acc[r][3]);
            float4 o0, o1;
            o0.x = fmaxf(f0.x + b[0], 0.0f);
            o0.y = fmaxf(f0.y + b[1], 0.0f);
            o0.z = fmaxf(f1.x + b[2], 0.0f);
            o0.w = fmaxf(f1.y + b[3], 0.0f);
            o1.x = fmaxf(f2.x + b[4], 0.0f);
            o1.y = fmaxf(f2.y + b[5], 0.0f);
            o1.z = fmaxf(f3.x + b[6], 0.0f);
            o1.w = fmaxf(f3.y + b[7], 0.0f);
            float4* cp = (float4*)&C[(size_t)row * 128 + cg * 8];
            cp[0] = o0;
            cp[1] = o1;
        }
    }
}

// ---------------- global add pool: pool[batch[n]] += h[n] ----------------
__global__ __launch_bounds__(256) void k_pool(const float* __restrict__ h,
                                              const void* __restrict__ batch) {
    int warp = (blockIdx.x * blockDim.x + threadIdx.x) >> 5;
    int lane = threadIdx.x & 31;
    if (warp >= N_NODES) return;
    int gidx = idx_at(batch, warp, g_is64);
    float4 v = ((const float4*)h)[(size_t)warp * 32 + lane];
    float* base = &g_pool[(size_t)gidx * 128 + lane * 4];
    atomicAdd(base + 0, v.x);
    atomicAdd(base + 1, v.y);
    atomicAdd(base + 2, v.z);
    atomicAdd(base + 3, v.w);
}

// ---------------- head: mu = g@W_mu+b_mu, lv = g@W_lv+b_lv ----------------
__global__ __launch_bounds__(128) void k_head(const float* __restrict__ Wmu,
                                              const float* __restrict__ bmu,
                                              const float* __restrict__ Wlv,
                                              const float* __restrict__ blv,
                                              float* __restrict__ out) {
    __shared__ float p[128];
    int g = blockIdx.x;
    p[threadIdx.x] = g_pool[(size_t)g * 128 + threadIdx.x];
    __syncthreads();
    int t = threadIdx.x;
    const float* W = (t < 64) ? Wmu : Wlv;
    const float* b = (t < 64) ? bmu : blv;
    int c = t & 63;
    float acc = 0.0f;
    #pragma unroll 8
    for (int k = 0; k < 128; k++) acc += p[k] * W[k * 64 + c];
    acc += b[c];
    size_t off = (t < 64) ? 0 : (size_t)N_GRAPHS * LAT;
    out[off + (size_t)g * 64 + c] = acc;
}

// ---------------- launch ----------------
extern "C" void kernel_launch(void* const* d_in, const int* in_sizes, int n_in,
                              void* d_out, int out_size) {
    const float* x    = (const float*)d_in[0];
    const void*  ei   = d_in[1];           // int32 or int64; detected in-graph
    const void*  bat  = d_in[2];
    const float* W1   = (const float*)d_in[3];
    const float* b1   = (const float*)d_in[4];
    const float* W2   = (const float*)d_in[5];
    const float* b2   = (const float*)d_in[6];
    const float* Wmu  = (const float*)d_in[7];
    const float* bmu  = (const float*)d_in[8];
    const float* Wlv  = (const float*)d_in[9];
    const float* blv  = (const float*)d_in[10];
    float*       out  = (float*)d_out;

    float *bufA, *bufB;
    cudaGetSymbolAddress((void**)&bufA, g_bufA);
    cudaGetSymbolAddress((void**)&bufB, g_bufB);

    // dtype detect + init + CSR build (per-launch; replay-safe)
    k_detect<<<1, 32>>>(ei);
    k_zero<<<(N_GRAPHS * HID + 255) / 256, 256>>>();
    k_hist<<<(N_EDGES + 255) / 256, 256>>>(ei);
    k_scan_local<<<SCAN_NB, SCAN_B>>>();
    k_scan_bsums<<<1, 32>>>();
    k_scan_add<<<SCAN_NB, SCAN_B>>>();
    k_scatter<<<(N_EDGES + 255) / 256, 256>>>(ei);

    const int aggGrid  = (N_NODES * 32 + 255) / 256;   // warp per node
    const int gemmGrid = (N_NODES + 63) / 64;

    // layer 0: x -> A -> B -> A
    k_agg<<<aggGrid, 256>>>(x, bufA);
    k_gemm_relu<<<gemmGrid, 256>>>(bufA, W1 + 0 * 128 * 128, b1 + 0 * 128, bufB);
    k_gemm_relu<<<gemmGrid, 256>>>(bufB, W2 + 0 * 128 * 128, b2 + 0 * 128, bufA);
    // layer 1
    k_agg<<<aggGrid, 256>>>(bufA, bufB);
    k_gemm_relu<<<gemmGrid, 256>>>(bufB, W1 + 1 * 128 * 128, b1 + 1 * 128, bufA);
    k_gemm_relu<<<gemmGrid, 256>>>(bufA, W2 + 1 * 128 * 128, b2 + 1 * 128, bufB);
    // layer 2
    k_agg<<<aggGrid, 256>>>(bufB, bufA);
    k_gemm_relu<<<gemmGrid, 256>>>(bufA, W1 + 2 * 128 * 128, b1 + 2 * 128, bufB);
    k_gemm_relu<<<gemmGrid, 256>>>(bufB, W2 + 2 * 128 * 128, b2 + 2 * 128, bufA);

    // pool + heads
    k_pool<<<aggGrid, 256>>>(bufA, bat);
    k_head<<<N_GRAPHS, 128>>>(Wmu, bmu, Wlv, blv, out);
}

// round 9
// speedup vs baseline: 1.9119x; 1.9119x over previous
#include <cuda_runtime.h>
#include <cuda_bf16.h>
#include <stdint.h>

#define N_NODES  100000
#define N_EDGES  1600000
#define IN_C     128
#define HID      128
#define LAT      64
#define N_LAYERS 3
#define N_GRAPHS 1000

#define SCAN_B   512
#define SCAN_NB  ((N_NODES + SCAN_B - 1) / SCAN_B)   // 196

#define WT_STRIDE 136                 // padded bf16 row stride (bank-conflict-free)
#define WT_ELEMS  (128 * WT_STRIDE)   // 17408 elems = 34816 B per image

// ---------------- scratch (device globals; no allocation allowed) ----------------
__device__ __align__(16) float g_bufA[N_NODES * HID];
__device__ __align__(16) float g_bufB[N_NODES * HID];
__device__ __align__(16) float g_pool[N_GRAPHS * HID];
__device__ __align__(16) __nv_bfloat16 g_wt_hi[6 * WT_ELEMS];  // W^T split images, padded
__device__ __align__(16) __nv_bfloat16 g_wt_lo[6 * WT_ELEMS];
__device__ int   g_deg[N_NODES];
__device__ int   g_rowptr[N_NODES + 1];
__device__ int   g_cursor[N_NODES];
__device__ int   g_col[N_EDGES];
__device__ int   g_bsums[SCAN_NB];
__device__ int   g_is64;   // 1 if indices are int64 on device, 0 if int32

// index loader that works for either int32 or int64 device layout
__device__ __forceinline__ int idx_at(const void* p, long long i, int is64) {
    if (is64) return (int)((const long long*)p)[i];
    return ((const int*)p)[i];
}

// ---------------- dtype detection (runs in-graph, deterministic) ----------------
__global__ void k_detect(const void* ei) {
    if (threadIdx.x == 0 && blockIdx.x == 0) {
        const long long* e64 = (const long long*)ei;
        int ok = 1;
        for (int i = 0; i < 256; i++) {
            long long v = e64[i];
            if (v < 0 || v >= N_NODES) { ok = 0; break; }
        }
        g_is64 = ok;
    }
}

// ---------------- init / CSR build ----------------
__global__ void k_zero() {
    int i = blockIdx.x * blockDim.x + threadIdx.x;
    if (i < N_NODES) g_deg[i] = 0;
    if (i < N_GRAPHS * HID) g_pool[i] = 0.0f;
}

__global__ void k_hist(const void* __restrict__ ei) {
    int e = blockIdx.x * blockDim.x + threadIdx.x;
    int is64 = g_is64;
    if (e < N_EDGES) {
        int dst = idx_at(ei, (long long)N_EDGES + e, is64);
        atomicAdd(&g_deg[dst], 1);
    }
}

__global__ void k_scan_local() {
    __shared__ int s[SCAN_B];
    int i = blockIdx.x * SCAN_B + threadIdx.x;
    int v = (i < N_NODES) ? g_deg[i] : 0;
    s[threadIdx.x] = v;
    __syncthreads();
    #pragma unroll
    for (int off = 1; off < SCAN_B; off <<= 1) {
        int t = (threadIdx.x >= off) ? s[threadIdx.x - off] : 0;
        __syncthreads();
        s[threadIdx.x] += t;
        __syncthreads();
    }
    if (i < N_NODES) g_rowptr[i] = s[threadIdx.x] - v;   // exclusive prefix
    if (threadIdx.x == SCAN_B - 1) g_bsums[blockIdx.x] = s[threadIdx.x];
}

__global__ void k_scan_bsums() {
    if (threadIdx.x == 0 && blockIdx.x == 0) {
        int acc = 0;
        for (int b = 0; b < SCAN_NB; b++) { int t = g_bsums[b]; g_bsums[b] = acc; acc += t; }
    }
}

__global__ void k_scan_add() {
    int i = blockIdx.x * SCAN_B + threadIdx.x;
    if (i < N_NODES) {
        int v = g_rowptr[i] + g_bsums[blockIdx.x];
        g_rowptr[i] = v;
        g_cursor[i] = v;
    }
    if (i == 0) g_rowptr[N_NODES] = N_EDGES;
}

__global__ void k_scatter(const void* __restrict__ ei) {
    int e = blockIdx.x * blockDim.x + threadIdx.x;
    int is64 = g_is64;
    if (e < N_EDGES) {
        int src = idx_at(ei, e, is64);
        int dst = idx_at(ei, (long long)N_EDGES + e, is64);
        int pos = atomicAdd(&g_cursor[dst], 1);
        g_col[pos] = src;
    }
}

// ---------------- weight prep: W^T + bf16 split into padded images --------------
// mat = l*2 + j (j=0 -> W1[l], j=1 -> W2[l]). Image layout: Wt[n][k], n = output col.
__global__ void k_wprep(const float* __restrict__ W1, const float* __restrict__ W2) {
    int idx = blockIdx.x * blockDim.x + threadIdx.x;
    if (idx >= 6 * 16384) return;
    int mat = idx >> 14;
    int rem = idx & 16383;
    int n = rem >> 7;         // output col = B row
    int k = rem & 127;        // K index
    int l = mat >> 1;
    const float* W = (mat & 1) ? W2 : W1;
    float v = W[l * 16384 + k * 128 + n];
    __nv_bfloat16 hi = __float2bfloat16_rn(v);
    __nv_bfloat16 lo = __float2bfloat16_rn(v - __bfloat162float(hi));
    int off = mat * WT_ELEMS + n * WT_STRIDE + k;
    g_wt_hi[off] = hi;
    g_wt_lo[off] = lo;
}

// ---------------- aggregation: agg[n] = h[n] + sum_{e in CSR(n)} h[col[e]] ----------------
__global__ __launch_bounds__(256) void k_agg(const float* __restrict__ h,
                                             float* __restrict__ out) {
    int warp = (blockIdx.x * blockDim.x + threadIdx.x) >> 5;
    int lane = threadIdx.x & 31;
    if (warp >= N_NODES) return;
    const float4* h4 = (const float4*)h;
    float4 acc = h4[(size_t)warp * 32 + lane];
    int s = g_rowptr[warp];
    int e = g_rowptr[warp + 1];
    int j = s;
    for (; j + 3 < e; j += 4) {
        int s0 = g_col[j];
        int s1 = g_col[j + 1];
        int s2 = g_col[j + 2];
        int s3 = g_col[j + 3];
        float4 v0 = h4[(size_t)s0 * 32 + lane];
        float4 v1 = h4[(size_t)s1 * 32 + lane];
        float4 v2 = h4[(size_t)s2 * 32 + lane];
        float4 v3 = h4[(size_t)s3 * 32 + lane];
        acc.x += (v0.x + v1.x) + (v2.x + v3.x);
        acc.y += (v0.y + v1.y) + (v2.y + v3.y);
        acc.z += (v0.z + v1.z) + (v2.z + v3.z);
        acc.w += (v0.w + v1.w) + (v2.w + v3.w);
    }
    for (; j < e; j++) {
        int s0 = g_col[j];
        float4 v0 = h4[(size_t)s0 * 32 + lane];
        acc.x += v0.x; acc.y += v0.y; acc.z += v0.z; acc.w += v0.w;
    }
    ((float4*)out)[(size_t)warp * 32 + lane] = acc;
}

// ---------------- HMMA GEMM + bias + ReLU:  C = relu(A @ W + b) ----------------
// 128x128 tile/block, 8 warps (2 m-groups x 4 n-groups), warp tile 64x32.
// mma.sync m16n8k16 bf16 -> fp32; split-bf16 3 passes (AhWh + AhWl + AlWh).
// smem: AsH, AsL, WtH, WtL each [128][136] bf16 -> 4 * 34816 = 139264 B dynamic.
__device__ __forceinline__ void mma16816(float* d, const uint32_t* a, const uint32_t* b) {
    asm volatile(
        "mma.sync.aligned.m16n8k16.row.col.f32.bf16.bf16.f32 "
        "{%0,%1,%2,%3}, {%4,%5,%6,%7}, {%8,%9}, {%0,%1,%2,%3};"
        : "+f"(d[0]), "+f"(d[1]), "+f"(d[2]), "+f"(d[3])
        : "r"(a[0]), "r"(a[1]), "r"(a[2]), "r"(a[3]), "r"(b[0]), "r"(b[1]));
}

__global__ __launch_bounds__(256) void k_tgemm(const float* __restrict__ A, int mat,
                                               const float* __restrict__ bias,
                                               float* __restrict__ C) {
    extern __shared__ __nv_bfloat16 sm[];
    __nv_bfloat16* AsH = sm;
    __nv_bfloat16* AsL = sm + WT_ELEMS;
    __nv_bfloat16* WtH = sm + 2 * WT_ELEMS;
    __nv_bfloat16* WtL = sm + 3 * WT_ELEMS;
    int tid = threadIdx.x;
    int rowBase = blockIdx.x * 128;

    // copy pre-split W^T images (34816 B each = 2176 uint4)
    {
        const uint4* gwh = (const uint4*)(g_wt_hi + mat * WT_ELEMS);
        const uint4* gwl = (const uint4*)(g_wt_lo + mat * WT_ELEMS);
        uint4* swh = (uint4*)WtH;
        uint4* swl = (uint4*)WtL;
        for (int i = tid; i < WT_ELEMS / 8; i += 256) {
            swh[i] = gwh[i];
            swl[i] = gwl[i];
        }
    }

    // load + split-convert A tile (128 rows x 128 K fp32 -> bf16 hi/lo, padded rows)
    {
        const float4* a4 = (const float4*)A;
        #pragma unroll
        for (int i = 0; i < 16; i++) {
            int idx = tid + i * 256;        // 0..4095
            int r = idx >> 5;               // 0..127
            int k4 = idx & 31;              // float4 index along K
            int grow = rowBase + r;
            float4 f = make_float4(0.f, 0.f, 0.f, 0.f);
            if (grow < N_NODES) f = a4[(size_t)grow * 32 + k4];
            __nv_bfloat16 h0 = __float2bfloat16_rn(f.x);
            __nv_bfloat16 h1 = __float2bfloat16_rn(f.y);
            __nv_bfloat16 h2 = __float2bfloat16_rn(f.z);
            __nv_bfloat16 h3 = __float2bfloat16_rn(f.w);
            __nv_bfloat16 l0 = __float2bfloat16_rn(f.x - __bfloat162float(h0));
            __nv_bfloat16 l1 = __float2bfloat16_rn(f.y - __bfloat162float(h1));
            __nv_bfloat16 l2 = __float2bfloat16_rn(f.z - __bfloat162float(h2));
            __nv_bfloat16 l3 = __float2bfloat16_rn(f.w - __bfloat162float(h3));
            uint2 uh, ul;
            uh.x = (uint32_t)__bfloat16_as_ushort(h0) | ((uint32_t)__bfloat16_as_ushort(h1) << 16);
            uh.y = (uint32_t)__bfloat16_as_ushort(h2) | ((uint32_t)__bfloat16_as_ushort(h3) << 16);
            ul.x = (uint32_t)__bfloat16_as_ushort(l0) | ((uint32_t)__bfloat16_as_ushort(l1) << 16);
            ul.y = (uint32_t)__bfloat16_as_ushort(l2) | ((uint32_t)__bfloat16_as_ushort(l3) << 16);
            int off = r * WT_STRIDE + k4 * 4;   // byte offset 2*off, 8B aligned (272r + 8k4)
            *(uint2*)(AsH + off) = uh;
            *(uint2*)(AsL + off) = ul;
        }
    }
    __syncthreads();

    int lane = tid & 31, wid = tid >> 5;
    int warpM = wid >> 2;          // 0..1
    int warpN = wid & 3;           // 0..3
    int g = lane >> 2, tig = lane & 3;

    float acc[4][4][4];            // [atomM][atomN][reg]
    #pragma unroll
    for (int am = 0; am < 4; am++)
        #pragma unroll
        for (int an = 0; an < 4; an++)
            #pragma unroll
            for (int q = 0; q < 4; q++) acc[am][an][q] = 0.0f;

    const int aRow0 = warpM * 64 + g;
    const int bN0   = warpN * 32 + g;

    #pragma unroll
    for (int pass = 0; pass < 3; pass++) {
        const __nv_bfloat16* Ab = (pass == 2) ? AsL : AsH;   // p0 hi*hi, p1 hi*lo, p2 lo*hi
        const __nv_bfloat16* Wb = (pass == 1) ? WtL : WtH;
        #pragma unroll
        for (int ks = 0; ks < 8; ks++) {
            int k0 = ks * 16 + tig * 2;
            uint32_t afr[4][4];
            #pragma unroll
            for (int am = 0; am < 4; am++) {
                const __nv_bfloat16* base = Ab + (aRow0 + am * 16) * WT_STRIDE + k0;
                afr[am][0] = *(const uint32_t*)(base);
                afr[am][1] = *(const uint32_t*)(base + 8 * WT_STRIDE);
                afr[am][2] = *(const uint32_t*)(base + 8);
                afr[am][3] = *(const uint32_t*)(base + 8 * WT_STRIDE + 8);
            }
            uint32_t bfr[4][2];
            #pragma unroll
            for (int an = 0; an < 4; an++) {
                const __nv_bfloat16* bb = Wb + (bN0 + an * 8) * WT_STRIDE + k0;
                bfr[an][0] = *(const uint32_t*)(bb);
                bfr[an][1] = *(const uint32_t*)(bb + 8);
            }
            #pragma unroll
            for (int am = 0; am < 4; am++)
                #pragma unroll
                for (int an = 0; an < 4; an++)
                    mma16816(acc[am][an], afr[am], bfr[an]);
        }
    }

    // epilogue: bias + ReLU, fragment store (float2 per half-atom)
    float bv0[4], bv1[4];
    #pragma unroll
    for (int an = 0; an < 4; an++) {
        int col = warpN * 32 + an * 8 + tig * 2;
        bv0[an] = __ldg(&bias[col]);
        bv1[an] = __ldg(&bias[col + 1]);
    }
    #pragma unroll
    for (int an = 0; an < 4; an++) {
        int col = warpN * 32 + an * 8 + tig * 2;
        #pragma unroll
        for (int am = 0; am < 4; am++) {
            int row0 = rowBase + warpM * 64 + am * 16 + g;
            if (row0 < N_NODES) {
                float2 o;
                o.x = fmaxf(acc[am][an][0] + bv0[an], 0.0f);
                o.y = fmaxf(acc[am][an][1] + bv1[an], 0.0f);
                *(float2*)&C[(size_t)row0 * 128 + col] = o;
            }
            int row1 = row0 + 8;
            if (row1 < N_NODES) {
                float2 o;
                o.x = fmaxf(acc[am][an][2] + bv0[an], 0.0f);
                o.y = fmaxf(acc[am][an][3] + bv1[an], 0.0f);
                *(float2*)&C[(size_t)row1 * 128 + col] = o;
            }
        }
    }
}

// ---------------- global add pool: pool[batch[n]] += h[n] ----------------
__global__ __launch_bounds__(256) void k_pool(const float* __restrict__ h,
                                              const void* __restrict__ batch) {
    int warp = (blockIdx.x * blockDim.x + threadIdx.x) >> 5;
    int lane = threadIdx.x & 31;
    if (warp >= N_NODES) return;
    int gidx = idx_at(batch, warp, g_is64);
    float4 v = ((const float4*)h)[(size_t)warp * 32 + lane];
    float* base = &g_pool[(size_t)gidx * 128 + lane * 4];
    atomicAdd(base + 0, v.x);
    atomicAdd(base + 1, v.y);
    atomicAdd(base + 2, v.z);
    atomicAdd(base + 3, v.w);
}

// ---------------- head: mu = g@W_mu+b_mu, lv = g@W_lv+b_lv ----------------
__global__ __launch_bounds__(128) void k_head(const float* __restrict__ Wmu,
                                              const float* __restrict__ bmu,
                                              const float* __restrict__ Wlv,
                                              const float* __restrict__ blv,
                                              float* __restrict__ out) {
    __shared__ float p[128];
    int g = blockIdx.x;
    p[threadIdx.x] = g_pool[(size_t)g * 128 + threadIdx.x];
    __syncthreads();
    int t = threadIdx.x;
    const float* W = (t < 64) ? Wmu : Wlv;
    const float* b = (t < 64) ? bmu : blv;
    int c = t & 63;
    float acc = 0.0f;
    #pragma unroll 8
    for (int k = 0; k < 128; k++) acc += p[k] * W[k * 64 + c];
    acc += b[c];
    size_t off = (t < 64) ? 0 : (size_t)N_GRAPHS * LAT;
    out[off + (size_t)g * 64 + c] = acc;
}

// ---------------- launch ----------------
extern "C" void kernel_launch(void* const* d_in, const int* in_sizes, int n_in,
                              void* d_out, int out_size) {
    const float* x    = (const float*)d_in[0];
    const void*  ei   = d_in[1];           // int32 or int64; detected in-graph
    const void*  bat  = d_in[2];
    const float* W1   = (const float*)d_in[3];
    const float* b1   = (const float*)d_in[4];
    const float* W2   = (const float*)d_in[5];
    const float* b2   = (const float*)d_in[6];
    const float* Wmu  = (const float*)d_in[7];
    const float* bmu  = (const float*)d_in[8];
    const float* Wlv  = (const float*)d_in[9];
    const float* blv  = (const float*)d_in[10];
    float*       out  = (float*)d_out;

    float *bufA, *bufB;
    cudaGetSymbolAddress((void**)&bufA, g_bufA);
    cudaGetSymbolAddress((void**)&bufB, g_bufB);

    const int TG_SMEM = 4 * WT_ELEMS * (int)sizeof(__nv_bfloat16);   // 139264 B
    cudaFuncSetAttribute(k_tgemm, cudaFuncAttributeMaxDynamicSharedMemorySize, TG_SMEM);

    // dtype detect + init + CSR build + weight prep (per-launch; replay-safe)
    k_detect<<<1, 32>>>(ei);
    k_zero<<<(N_GRAPHS * HID + 255) / 256, 256>>>();
    k_hist<<<(N_EDGES + 255) / 256, 256>>>(ei);
    k_scan_local<<<SCAN_NB, SCAN_B>>>();
    k_scan_bsums<<<1, 32>>>();
    k_scan_add<<<SCAN_NB, SCAN_B>>>();
    k_scatter<<<(N_EDGES + 255) / 256, 256>>>(ei);
    k_wprep<<<(6 * 16384 + 255) / 256, 256>>>(W1, W2);

    const int aggGrid  = (N_NODES * 32 + 255) / 256;   // warp per node
    const int tgGrid   = (N_NODES + 127) / 128;        // 782

    // layer 0: x -> A(agg) -> B -> A
    k_agg<<<aggGrid, 256>>>(x, bufA);
    k_tgemm<<<tgGrid, 256, TG_SMEM>>>(bufA, 0, b1 + 0 * 128, bufB);
    k_tgemm<<<tgGrid, 256, TG_SMEM>>>(bufB, 1, b2 + 0 * 128, bufA);
    // layer 1
    k_agg<<<aggGrid, 256>>>(bufA, bufB);
    k_tgemm<<<tgGrid, 256, TG_SMEM>>>(bufB, 2, b1 + 1 * 128, bufA);
    k_tgemm<<<tgGrid, 256, TG_SMEM>>>(bufA, 3, b2 + 1 * 128, bufB);
    // layer 2
    k_agg<<<aggGrid, 256>>>(bufB, bufA);
    k_tgemm<<<tgGrid, 256, TG_SMEM>>>(bufA, 4, b1 + 2 * 128, bufB);
    k_tgemm<<<tgGrid, 256, TG_SMEM>>>(bufB, 5, b2 + 2 * 128, bufA);

    // pool + heads
    k_pool<<<aggGrid, 256>>>(bufA, bat);
    k_head<<<N_GRAPHS, 128>>>(Wmu, bmu, Wlv, blv, out);
}

// round 10
// speedup vs baseline: 2.3228x; 1.2149x over previous
#include <cuda_runtime.h>
#include <cuda_bf16.h>
#include <stdint.h>

#define N_NODES  100000
#define N_EDGES  1600000
#define IN_C     128
#define HID      128
#define LAT      64
#define N_LAYERS 3
#define N_GRAPHS 1000

#define SCAN_B   512
#define SCAN_NB  ((N_NODES + SCAN_B - 1) / SCAN_B)   // 196

#define WTC_STRIDE 72                  // padded bf16 row stride per 64-K chunk
#define WTC_ELEMS  (128 * WTC_STRIDE)  // 9216 elems = 18432 B per image chunk

// ---------------- scratch (device globals; no allocation allowed) ----------------
__device__ __align__(16) float g_bufA[N_NODES * HID];
__device__ __align__(16) float g_bufB[N_NODES * HID];
__device__ __align__(16) float g_pool[N_GRAPHS * HID];
__device__ __align__(16) __nv_bfloat16 g_wt_hi[12 * WTC_ELEMS];  // [mat*2+chunk] images
__device__ __align__(16) __nv_bfloat16 g_wt_lo[12 * WTC_ELEMS];
__device__ int   g_deg[N_NODES];
__device__ int   g_rowptr[N_NODES + 1];
__device__ int   g_cursor[N_NODES];
__device__ int   g_col[N_EDGES];
__device__ int   g_bsums[SCAN_NB];
__device__ int   g_is64;   // 1 if indices are int64 on device, 0 if int32

__device__ __forceinline__ int idx_at(const void* p, long long i, int is64) {
    if (is64) return (int)((const long long*)p)[i];
    return ((const int*)p)[i];
}

// ---------------- init: dtype detect + zero deg/pool (one launch) ----------------
__global__ void k_dzero(const void* ei) {
    int i = blockIdx.x * blockDim.x + threadIdx.x;
    if (i == 0) {
        const long long* e64 = (const long long*)ei;
        int ok = 1;
        for (int q = 0; q < 256; q++) {
            long long v = e64[q];
            if (v < 0 || v >= N_NODES) { ok = 0; break; }
        }
        g_is64 = ok;
    }
    if (i < N_NODES) g_deg[i] = 0;
    if (i < N_GRAPHS * HID) g_pool[i] = 0.0f;
}

__global__ void k_hist(const void* __restrict__ ei) {
    int e = blockIdx.x * blockDim.x + threadIdx.x;
    int is64 = g_is64;
    if (e < N_EDGES) {
        int dst = idx_at(ei, (long long)N_EDGES + e, is64);
        atomicAdd(&g_deg[dst], 1);
    }
}

__global__ void k_scan_local() {
    __shared__ int s[SCAN_B];
    int i = blockIdx.x * SCAN_B + threadIdx.x;
    int v = (i < N_NODES) ? g_deg[i] : 0;
    s[threadIdx.x] = v;
    __syncthreads();
    #pragma unroll
    for (int off = 1; off < SCAN_B; off <<= 1) {
        int t = (threadIdx.x >= off) ? s[threadIdx.x - off] : 0;
        __syncthreads();
        s[threadIdx.x] += t;
        __syncthreads();
    }
    if (i < N_NODES) g_rowptr[i] = s[threadIdx.x] - v;   // exclusive (block-local)
    if (threadIdx.x == SCAN_B - 1) g_bsums[blockIdx.x] = s[threadIdx.x];
}

// each block self-sums preceding block totals (merges old bsums+scan_add kernels)
__global__ void k_scan_add2() {
    __shared__ int pref;
    if (threadIdx.x < 32) {
        int acc = 0;
        for (int b = threadIdx.x; b < blockIdx.x; b += 32) acc += g_bsums[b];
        #pragma unroll
        for (int o = 16; o > 0; o >>= 1) acc += __shfl_down_sync(0xFFFFFFFF, acc, o);
        if (threadIdx.x == 0) pref = acc;
    }
    __syncthreads();
    int i = blockIdx.x * SCAN_B + threadIdx.x;
    if (i < N_NODES) {
        int v = g_rowptr[i] + pref;
        g_rowptr[i] = v;
        g_cursor[i] = v;
    }
    if (i == 0) g_rowptr[N_NODES] = N_EDGES;
}

__global__ void k_scatter(const void* __restrict__ ei) {
    int e = blockIdx.x * blockDim.x + threadIdx.x;
    int is64 = g_is64;
    if (e < N_EDGES) {
        int src = idx_at(ei, e, is64);
        int dst = idx_at(ei, (long long)N_EDGES + e, is64);
        int pos = atomicAdd(&g_cursor[dst], 1);
        g_col[pos] = src;
    }
}

// ---------------- weight prep: W^T + bf16 split into chunked padded images ------
// image index = mat*2 + chunk; layout [n][klocal] with stride WTC_STRIDE.
__global__ void k_wprep(const float* __restrict__ W1, const float* __restrict__ W2) {
    int idx = blockIdx.x * blockDim.x + threadIdx.x;
    if (idx >= 6 * 16384) return;
    int mat = idx >> 14;
    int rem = idx & 16383;
    int n = rem >> 7;         // output col = B row
    int k = rem & 127;        // global K index
    int l = mat >> 1;
    const float* W = (mat & 1) ? W2 : W1;
    float v = W[l * 16384 + k * 128 + n];
    __nv_bfloat16 hi = __float2bfloat16_rn(v);
    __nv_bfloat16 lo = __float2bfloat16_rn(v - __bfloat162float(hi));
    int chunk = k >> 6, kl = k & 63;
    int off = (mat * 2 + chunk) * WTC_ELEMS + n * WTC_STRIDE + kl;
    g_wt_hi[off] = hi;
    g_wt_lo[off] = lo;
}

// ---------------- aggregation: agg[n] = h[n] + sum_{e in CSR(n)} h[col[e]] -------
// warp per node; lane owns one float4; 8-way unroll with up-front col prefetch
__global__ __launch_bounds__(256) void k_agg(const float* __restrict__ h,
                                             float* __restrict__ out) {
    int warp = (blockIdx.x * blockDim.x + threadIdx.x) >> 5;
    int lane = threadIdx.x & 31;
    if (warp >= N_NODES) return;
    const float4* h4 = (const float4*)h;
    float4 acc = h4[(size_t)warp * 32 + lane];
    int s = g_rowptr[warp];
    int e = g_rowptr[warp + 1];
    int j = s;
    for (; j + 7 < e; j += 8) {
        int c0 = g_col[j + 0], c1 = g_col[j + 1], c2 = g_col[j + 2], c3 = g_col[j + 3];
        int c4 = g_col[j + 4], c5 = g_col[j + 5], c6 = g_col[j + 6], c7 = g_col[j + 7];
        float4 v0 = h4[(size_t)c0 * 32 + lane];
        float4 v1 = h4[(size_t)c1 * 32 + lane];
        float4 v2 = h4[(size_t)c2 * 32 + lane];
        float4 v3 = h4[(size_t)c3 * 32 + lane];
        float4 v4 = h4[(size_t)c4 * 32 + lane];
        float4 v5 = h4[(size_t)c5 * 32 + lane];
        float4 v6 = h4[(size_t)c6 * 32 + lane];
        float4 v7 = h4[(size_t)c7 * 32 + lane];
        acc.x += ((v0.x + v1.x) + (v2.x + v3.x)) + ((v4.x + v5.x) + (v6.x + v7.x));
        acc.y += ((v0.y + v1.y) + (v2.y + v3.y)) + ((v4.y + v5.y) + (v6.y + v7.y));
        acc.z += ((v0.z + v1.z) + (v2.z + v3.z)) + ((v4.z + v5.z) + (v6.z + v7.z));
        acc.w += ((v0.w + v1.w) + (v2.w + v3.w)) + ((v4.w + v5.w) + (v6.w + v7.w));
    }
    for (; j + 1 < e; j += 2) {
        int c0 = g_col[j], c1 = g_col[j + 1];
        float4 v0 = h4[(size_t)c0 * 32 + lane];
        float4 v1 = h4[(size_t)c1 * 32 + lane];
        acc.x += v0.x + v1.x; acc.y += v0.y + v1.y;
        acc.z += v0.z + v1.z; acc.w += v0.w + v1.w;
    }
    if (j < e) {
        int c0 = g_col[j];
        float4 v0 = h4[(size_t)c0 * 32 + lane];
        acc.x += v0.x; acc.y += v0.y; acc.z += v0.z; acc.w += v0.w;
    }
    ((float4*)out)[(size_t)warp * 32 + lane] = acc;
}

// ---------------- HMMA GEMM + bias + ReLU (+optional fused pool) -----------------
// 128x128 tile/block, 8 warps (2x4), warp tile 64x32; K processed in 2 chunks of 64
// to halve smem (73728 B -> 2 blocks/SM). Split-bf16 3 passes, fp32 accumulators.
__device__ __forceinline__ void mma16816(float* d, const uint32_t* a, const uint32_t* b) {
    asm volatile(
        "mma.sync.aligned.m16n8k16.row.col.f32.bf16.bf16.f32 "
        "{%0,%1,%2,%3}, {%4,%5,%6,%7}, {%8,%9}, {%0,%1,%2,%3};"
        : "+f"(d[0]), "+f"(d[1]), "+f"(d[2]), "+f"(d[3])
        : "r"(a[0]), "r"(a[1]), "r"(a[2]), "r"(a[3]), "r"(b[0]), "r"(b[1]));
}

__global__ __launch_bounds__(256) void k_tgemm(const float* __restrict__ A, int mat,
                                               const float* __restrict__ bias,
                                               float* __restrict__ C,
                                               const void* __restrict__ batch,
                                               int do_pool) {
    extern __shared__ __nv_bfloat16 sm[];
    __nv_bfloat16* AsH = sm;
    __nv_bfloat16* AsL = sm + WTC_ELEMS;
    __nv_bfloat16* WtH = sm + 2 * WTC_ELEMS;
    __nv_bfloat16* WtL = sm + 3 * WTC_ELEMS;
    int tid = threadIdx.x;
    int rowBase = blockIdx.x * 128;
    int lane = tid & 31, wid = tid >> 5;
    int warpM = wid >> 2;          // 0..1
    int warpN = wid & 3;           // 0..3
    int g = lane >> 2, tig = lane & 3;
    const int aRow0 = warpM * 64 + g;
    const int bN0   = warpN * 32 + g;

    float acc[4][4][4];
    #pragma unroll
    for (int am = 0; am < 4; am++)
        #pragma unroll
        for (int an = 0; an < 4; an++)
            #pragma unroll
            for (int q = 0; q < 4; q++) acc[am][an][q] = 0.0f;

    #pragma unroll
    for (int chunk = 0; chunk < 2; chunk++) {
        if (chunk) __syncthreads();   // drain previous chunk's MMA reads before overwrite

        // copy W chunk images (18432 B each = 1152 uint4)
        {
            const uint4* gwh = (const uint4*)(g_wt_hi + (mat * 2 + chunk) * WTC_ELEMS);
            const uint4* gwl = (const uint4*)(g_wt_lo + (mat * 2 + chunk) * WTC_ELEMS);
            uint4* swh = (uint4*)WtH;
            uint4* swl = (uint4*)WtL;
            #pragma unroll
            for (int i = 0; i < 5; i++) {
                int idx = tid + i * 256;
                if (idx < WTC_ELEMS / 8) { swh[idx] = gwh[idx]; swl[idx] = gwl[idx]; }
            }
        }

        // load + split-convert A chunk (128 rows x 64 K): 2048 float4
        {
            const float4* a4 = (const float4*)A;
            #pragma unroll
            for (int i = 0; i < 8; i++) {
                int idx = tid + i * 256;        // 0..2047
                int r = idx >> 4;               // 0..127
                int k4 = idx & 15;              // float4 within chunk
                int grow = rowBase + r;
                float4 f = make_float4(0.f, 0.f, 0.f, 0.f);
                if (grow < N_NODES) f = a4[(size_t)grow * 32 + chunk * 16 + k4];
                __nv_bfloat16 h0 = __float2bfloat16_rn(f.x);
                __nv_bfloat16 h1 = __float2bfloat16_rn(f.y);
                __nv_bfloat16 h2 = __float2bfloat16_rn(f.z);
                __nv_bfloat16 h3 = __float2bfloat16_rn(f.w);
                __nv_bfloat16 l0 = __float2bfloat16_rn(f.x - __bfloat162float(h0));
                __nv_bfloat16 l1 = __float2bfloat16_rn(f.y - __bfloat162float(h1));
                __nv_bfloat16 l2 = __float2bfloat16_rn(f.z - __bfloat162float(h2));
                __nv_bfloat16 l3 = __float2bfloat16_rn(f.w - __bfloat162float(h3));
                uint2 uh, ul;
                uh.x = (uint32_t)__bfloat16_as_ushort(h0) | ((uint32_t)__bfloat16_as_ushort(h1) << 16);
                uh.y = (uint32_t)__bfloat16_as_ushort(h2) | ((uint32_t)__bfloat16_as_ushort(h3) << 16);
                ul.x = (uint32_t)__bfloat16_as_ushort(l0) | ((uint32_t)__bfloat16_as_ushort(l1) << 16);
                ul.y = (uint32_t)__bfloat16_as_ushort(l2) | ((uint32_t)__bfloat16_as_ushort(l3) << 16);
                int off = r * WTC_STRIDE + k4 * 4;   // byte 144r + 8k4, 8B aligned
                *(uint2*)(AsH + off) = uh;
                *(uint2*)(AsL + off) = ul;
            }
        }
        __syncthreads();

        #pragma unroll
        for (int pass = 0; pass < 3; pass++) {
            const __nv_bfloat16* Ab = (pass == 2) ? AsL : AsH;   // AhWh, AhWl, AlWh
            const __nv_bfloat16* Wb = (pass == 1) ? WtL : WtH;
            #pragma unroll
            for (int ks = 0; ks < 4; ks++) {
                int k0 = ks * 16 + tig * 2;
                uint32_t afr[4][4];
                #pragma unroll
                for (int am = 0; am < 4; am++) {
                    const __nv_bfloat16* base = Ab + (aRow0 + am * 16) * WTC_STRIDE + k0;
                    afr[am][0] = *(const uint32_t*)(base);
                    afr[am][1] = *(const uint32_t*)(base + 8 * WTC_STRIDE);
                    afr[am][2] = *(const uint32_t*)(base + 8);
                    afr[am][3] = *(const uint32_t*)(base + 8 * WTC_STRIDE + 8);
                }
                uint32_t bfr[4][2];
                #pragma unroll
                for (int an = 0; an < 4; an++) {
                    const __nv_bfloat16* bb = Wb + (bN0 + an * 8) * WTC_STRIDE + k0;
                    bfr[an][0] = *(const uint32_t*)(bb);
                    bfr[an][1] = *(const uint32_t*)(bb + 8);
                }
                #pragma unroll
                for (int am = 0; am < 4; am++)
                    #pragma unroll
                    for (int an = 0; an < 4; an++)
                        mma16816(acc[am][an], afr[am], bfr[an]);
            }
        }
    }

    // epilogue: bias + ReLU, then either store C or fused pool atomics
    float bv0[4], bv1[4];
    #pragma unroll
    for (int an = 0; an < 4; an++) {
        int col = warpN * 32 + an * 8 + tig * 2;
        bv0[an] = __ldg(&bias[col]);
        bv1[an] = __ldg(&bias[col + 1]);
    }
    if (!do_pool) {
        #pragma unroll
        for (int an = 0; an < 4; an++) {
            int col = warpN * 32 + an * 8 + tig * 2;
            #pragma unroll
            for (int am = 0; am < 4; am++) {
                int row0 = rowBase + warpM * 64 + am * 16 + g;
                if (row0 < N_NODES) {
                    float2 o;
                    o.x = fmaxf(acc[am][an][0] + bv0[an], 0.0f);
                    o.y = fmaxf(acc[am][an][1] + bv1[an], 0.0f);
                    *(float2*)&C[(size_t)row0 * 128 + col] = o;
                }
                int row1 = row0 + 8;
                if (row1 < N_NODES) {
                    float2 o;
                    o.x = fmaxf(acc[am][an][2] + bv0[an], 0.0f);
                    o.y = fmaxf(acc[am][an][3] + bv1[an], 0.0f);
                    *(float2*)&C[(size_t)row1 * 128 + col] = o;
                }
            }
        }
    } else {
        int is64 = g_is64;
        #pragma unroll
        for (int am = 0; am < 4; am++) {
            int row0 = rowBase + warpM * 64 + am * 16 + g;
            int row1 = row0 + 8;
            int g0 = (row0 < N_NODES) ? idx_at(batch, row0, is64) : -1;
            int g1 = (row1 < N_NODES) ? idx_at(batch, row1, is64) : -1;
            #pragma unroll
            for (int an = 0; an < 4; an++) {
                int col = warpN * 32 + an * 8 + tig * 2;
                if (g0 >= 0) {
                    atomicAdd(&g_pool[(size_t)g0 * 128 + col],     fmaxf(acc[am][an][0] + bv0[an], 0.0f));
                    atomicAdd(&g_pool[(size_t)g0 * 128 + col + 1], fmaxf(acc[am][an][1] + bv1[an], 0.0f));
                }
                if (g1 >= 0) {
                    atomicAdd(&g_pool[(size_t)g1 * 128 + col],     fmaxf(acc[am][an][2] + bv0[an], 0.0f));
                    atomicAdd(&g_pool[(size_t)g1 * 128 + col + 1], fmaxf(acc[am][an][3] + bv1[an], 0.0f));
                }
            }
        }
    }
}

// ---------------- head: mu = g@W_mu+b_mu, lv = g@W_lv+b_lv ----------------
__global__ __launch_bounds__(128) void k_head(const float* __restrict__ Wmu,
                                              const float* __restrict__ bmu,
                                              const float* __restrict__ Wlv,
                                              const float* __restrict__ blv,
                                              float* __restrict__ out) {
    __shared__ float p[128];
    int g = blockIdx.x;
    p[threadIdx.x] = g_pool[(size_t)g * 128 + threadIdx.x];
    __syncthreads();
    int t = threadIdx.x;
    const float* W = (t < 64) ? Wmu : Wlv;
    const float* b = (t < 64) ? bmu : blv;
    int c = t & 63;
    float acc = 0.0f;
    #pragma unroll 8
    for (int k = 0; k < 128; k++) acc += p[k] * W[k * 64 + c];
    acc += b[c];
    size_t off = (t < 64) ? 0 : (size_t)N_GRAPHS * LAT;
    out[off + (size_t)g * 64 + c] = acc;
}

// ---------------- launch ----------------
extern "C" void kernel_launch(void* const* d_in, const int* in_sizes, int n_in,
                              void* d_out, int out_size) {
    const float* x    = (const float*)d_in[0];
    const void*  ei   = d_in[1];           // int32 or int64; detected in-graph
    const void*  bat  = d_in[2];
    const float* W1   = (const float*)d_in[3];
    const float* b1   = (const float*)d_in[4];
    const float* W2   = (const float*)d_in[5];
    const float* b2   = (const float*)d_in[6];
    const float* Wmu  = (const float*)d_in[7];
    const float* bmu  = (const float*)d_in[8];
    const float* Wlv  = (const float*)d_in[9];
    const float* blv  = (const float*)d_in[10];
    float*       out  = (float*)d_out;

    float *bufA, *bufB;
    cudaGetSymbolAddress((void**)&bufA, g_bufA);
    cudaGetSymbolAddress((void**)&bufB, g_bufB);

    const int TG_SMEM = 4 * WTC_ELEMS * (int)sizeof(__nv_bfloat16);   // 73728 B
    cudaFuncSetAttribute(k_tgemm, cudaFuncAttributeMaxDynamicSharedMemorySize, TG_SMEM);

    // init + CSR build (per-launch; replay-safe)
    k_dzero<<<(N_GRAPHS * HID + 255) / 256, 256>>>(ei);
    k_hist<<<(N_EDGES + 255) / 256, 256>>>(ei);
    k_scan_local<<<SCAN_NB, SCAN_B>>>();
    k_scan_add2<<<SCAN_NB, SCAN_B>>>();
    k_scatter<<<(N_EDGES + 255) / 256, 256>>>(ei);

    const int aggGrid  = (N_NODES * 32 + 255) / 256;   // warp per node
    const int tgGrid   = (N_NODES + 127) / 128;        // 782

    // layer 0: x -> A(agg) -> B -> A   (wprep after first agg, before first GEMM)
    k_agg<<<aggGrid, 256>>>(x, bufA);
    k_wprep<<<(6 * 16384 + 255) / 256, 256>>>(W1, W2);
    k_tgemm<<<tgGrid, 256, TG_SMEM>>>(bufA, 0, b1 + 0 * 128, bufB, bat, 0);
    k_tgemm<<<tgGrid, 256, TG_SMEM>>>(bufB, 1, b2 + 0 * 128, bufA, bat, 0);
    // layer 1
    k_agg<<<aggGrid, 256>>>(bufA, bufB);
    k_tgemm<<<tgGrid, 256, TG_SMEM>>>(bufB, 2, b1 + 1 * 128, bufA, bat, 0);
    k_tgemm<<<tgGrid, 256, TG_SMEM>>>(bufA, 3, b2 + 1 * 128, bufB, bat, 0);
    // layer 2 (last GEMM fuses global add pool; no C write)
    k_agg<<<aggGrid, 256>>>(bufB, bufA);
    k_tgemm<<<tgGrid, 256, TG_SMEM>>>(bufA, 4, b1 + 2 * 128, bufB, bat, 0);
    k_tgemm<<<tgGrid, 256, TG_SMEM>>>(bufB, 5, b2 + 2 * 128, bufA, bat, 1);

    // heads
    k_head<<<N_GRAPHS, 128>>>(Wmu, bmu, Wlv, blv, out);
}